// round 5
// baseline (speedup 1.0000x reference)
#include <cuda_runtime.h>
#include <cuda_bf16.h>

// Problem constants
#define M_ROWS  200000      // BATCH * SIM_T
#define K_DIM   784
#define N1      100
#define T_STEPS 2000
#define BATCH   100
#define N2      10

// Scratch (z1 padded by 4 rows so the scan prefetch needs no bounds check)
__device__ float g_z1[(size_t)(M_ROWS + 4) * N1];           // 80 MB
__device__ __nv_bfloat16 g_W1h[112 * K_DIM];                // W1 hi split
__device__ __nv_bfloat16 g_W1l[112 * K_DIM];                // W1 lo split

// ---------------------------------------------------------------------------
// helpers
// ---------------------------------------------------------------------------
__device__ __forceinline__ unsigned pack_bf16x2(float fhi, float flo) {
    unsigned r;
    asm("cvt.rn.bf16x2.f32 %0, %1, %2;" : "=r"(r) : "f"(fhi), "f"(flo));
    return r;
}
__device__ __forceinline__ void mma_bf16(float* c, const unsigned* a,
                                         unsigned b0, unsigned b1) {
    asm("mma.sync.aligned.m16n8k16.row.col.f32.bf16.bf16.f32 "
        "{%0,%1,%2,%3}, {%4,%5,%6,%7}, {%8,%9}, {%0,%1,%2,%3};"
        : "+f"(c[0]), "+f"(c[1]), "+f"(c[2]), "+f"(c[3])
        : "r"(a[0]), "r"(a[1]), "r"(a[2]), "r"(a[3]), "r"(b0), "r"(b1));
}

// ---------------------------------------------------------------------------
// K0: convert W1 (100x784 fp32) -> bf16 hi/lo, padded to 112 rows
// ---------------------------------------------------------------------------
__global__ void w1_convert_kernel(const float* __restrict__ W1) {
    int idx = blockIdx.x * 256 + threadIdx.x;
    if (idx >= 112 * K_DIM) return;
    int r = idx / K_DIM;
    float w = (r < N1) ? W1[idx] : 0.f;
    __nv_bfloat16 hb = __float2bfloat16_rn(w);
    float hf = __bfloat162float(hb);
    g_W1h[idx] = hb;
    g_W1l[idx] = __float2bfloat16_rn(w - hf);
}

// ---------------------------------------------------------------------------
// K1: tensor-core GEMM  z1[M,100] = A[M,784] @ W1^T   (bf16 3-split, fp32 acc)
// (unchanged from round 4 — known good)
// ---------------------------------------------------------------------------
#define NSTAGE 49   // 784/16

__global__ void __launch_bounds__(256, 2)
gemm_z1_tc(const float* __restrict__ A) {
    __shared__ unsigned Ah[2][128 * 8];
    __shared__ unsigned Al[2][128 * 8];
    __shared__ unsigned Bh[2][112 * 8];
    __shared__ unsigned Bl[2][112 * 8];

    const int tid  = threadIdx.x;
    const int warp = tid >> 5, lane = tid & 31;
    const int g    = lane >> 2, tig = lane & 3;
    const int wm   = (warp >> 1) * 32;
    const int wn   = (warp & 1) * 56;
    const int row0 = blockIdx.x * 128;

    float acc[2][7][4];
#pragma unroll
    for (int i = 0; i < 2; i++)
#pragma unroll
        for (int j = 0; j < 7; j++)
#pragma unroll
            for (int q = 0; q < 4; q++) acc[i][j][q] = 0.f;

    float4 va[2];
    unsigned vbh[4], vbl[4];

    auto ldg_stage = [&](int s) {
        int k0 = s * 16;
#pragma unroll
        for (int i = 0; i < 2; i++) {
            int idx = tid + i * 256;
            int r = idx >> 2, q = idx & 3;
            int gr = row0 + r;
            va[i] = (gr < M_ROWS)
                  ? *(const float4*)(A + (size_t)gr * K_DIM + k0 + 4 * q)
                  : make_float4(0.f, 0.f, 0.f, 0.f);
        }
#pragma unroll
        for (int i = 0; i < 4; i++) {
            int idx = tid + i * 256;
            if (idx < 896) {
                int r = idx >> 3, j = idx & 7;
                size_t off = (size_t)r * (K_DIM / 2) + (k0 >> 1) + j;
                vbh[i] = ((const unsigned*)g_W1h)[off];
                vbl[i] = ((const unsigned*)g_W1l)[off];
            }
        }
    };
    auto sts_stage = [&](int buf) {
#pragma unroll
        for (int i = 0; i < 2; i++) {
            int idx = tid + i * 256;
            int r = idx >> 2, q = idx & 3;
            float4 v = va[i];
            unsigned h0 = pack_bf16x2(v.y, v.x);
            unsigned h1 = pack_bf16x2(v.w, v.z);
            float f0h = __uint_as_float(h0 << 16);
            float f1h = __uint_as_float(h0 & 0xffff0000u);
            float f2h = __uint_as_float(h1 << 16);
            float f3h = __uint_as_float(h1 & 0xffff0000u);
            unsigned l0 = pack_bf16x2(v.y - f1h, v.x - f0h);
            unsigned l1 = pack_bf16x2(v.w - f3h, v.z - f2h);
            int sw = r & 7;
            Ah[buf][r * 8 + ((2 * q)     ^ sw)] = h0;
            Ah[buf][r * 8 + ((2 * q + 1) ^ sw)] = h1;
            Al[buf][r * 8 + ((2 * q)     ^ sw)] = l0;
            Al[buf][r * 8 + ((2 * q + 1) ^ sw)] = l1;
        }
#pragma unroll
        for (int i = 0; i < 4; i++) {
            int idx = tid + i * 256;
            if (idx < 896) {
                int r = idx >> 3, j = idx & 7;
                Bh[buf][r * 8 + (j ^ (r & 7))] = vbh[i];
                Bl[buf][r * 8 + (j ^ (r & 7))] = vbl[i];
            }
        }
    };

    ldg_stage(0);
    sts_stage(0);
    __syncthreads();

#pragma unroll 1
    for (int s = 0; s < NSTAGE; s++) {
        if (s + 1 < NSTAGE) ldg_stage(s + 1);

        const int buf = s & 1;
        unsigned a_h[2][4], a_l[2][4];
#pragma unroll
        for (int mt = 0; mt < 2; mt++) {
            int r0 = wm + mt * 16 + g, r1 = r0 + 8;
            int s0 = r0 & 7, s1 = r1 & 7;
            a_h[mt][0] = Ah[buf][r0 * 8 + (tig ^ s0)];
            a_h[mt][1] = Ah[buf][r1 * 8 + (tig ^ s1)];
            a_h[mt][2] = Ah[buf][r0 * 8 + ((tig + 4) ^ s0)];
            a_h[mt][3] = Ah[buf][r1 * 8 + ((tig + 4) ^ s1)];
            a_l[mt][0] = Al[buf][r0 * 8 + (tig ^ s0)];
            a_l[mt][1] = Al[buf][r1 * 8 + (tig ^ s1)];
            a_l[mt][2] = Al[buf][r0 * 8 + ((tig + 4) ^ s0)];
            a_l[mt][3] = Al[buf][r1 * 8 + ((tig + 4) ^ s1)];
        }
#pragma unroll
        for (int nt = 0; nt < 7; nt++) {
            int n = wn + nt * 8 + g;
            int sn = n & 7;
            unsigned b0h = Bh[buf][n * 8 + (tig ^ sn)];
            unsigned b1h = Bh[buf][n * 8 + ((tig + 4) ^ sn)];
            unsigned b0l = Bl[buf][n * 8 + (tig ^ sn)];
            unsigned b1l = Bl[buf][n * 8 + ((tig + 4) ^ sn)];
#pragma unroll
            for (int mt = 0; mt < 2; mt++) {
                mma_bf16(acc[mt][nt], a_h[mt], b0h, b1h);
                mma_bf16(acc[mt][nt], a_h[mt], b0l, b1l);
                mma_bf16(acc[mt][nt], a_l[mt], b0h, b1h);
            }
        }

        if (s + 1 < NSTAGE) sts_stage((s + 1) & 1);
        __syncthreads();
    }

#pragma unroll
    for (int mt = 0; mt < 2; mt++) {
#pragma unroll
        for (int nt = 0; nt < 7; nt++) {
            int c = wn + nt * 8 + 2 * tig;
            if (c >= 99) continue;
            int r0g = row0 + wm + mt * 16 + g;
            if (r0g < M_ROWS) {
                float2 v = make_float2(acc[mt][nt][0], acc[mt][nt][1]);
                *(float2*)(g_z1 + (size_t)r0g * N1 + c) = v;
            }
            if (r0g + 8 < M_ROWS) {
                float2 v = make_float2(acc[mt][nt][2], acc[mt][nt][3]);
                *(float2*)(g_z1 + (size_t)(r0g + 8) * N1 + c) = v;
            }
        }
    }
}

// ---------------------------------------------------------------------------
// HH step — single EX2 + single RCP per gate (round-3 math)
// ---------------------------------------------------------------------------
__device__ __forceinline__ float ex2a(float x) {
    float r; asm("ex2.approx.f32 %0, %1;" : "=f"(r) : "f"(x)); return r;
}
__device__ __forceinline__ float rcpa(float x) {
    float r; asm("rcp.approx.f32 %0, %1;" : "=f"(r) : "f"(x)); return r;
}

#define L9   0.1602994489863f
#define L12  0.1202245867397f
#define L3   0.4808983469589f
#define BH_C 0.0023508962f
#define S0V  9.357622969e-14f

__device__ __forceinline__ void hh_step(float zk, float& V, float& m, float& n, float& h) {
    float mm   = m * m;
    float pow1 = 40.f * (mm * m) * h;
    float nn   = n * n;
    float pow2 = 35.f * (nn * nn);
    float Gs = 0.005f * (pow1 + pow2 + 0.3f);
    float E  = fmaf(pow1, 55.f, fmaf(pow2, -77.f, -19.5f));
    float num = fmaf(V, (1.f - Gs), 0.01f * (E + 1.5f + zk));
    float Vn = num * rcpa(1.f + Gs);

    float dM = Vn + 35.f;
    float uM = ex2a(dM * L9);
    float um1M = uM - 1.f;
    float sM = 0.005f * dM * fmaf(0.182f, uM, 0.124f);
    float mN = fmaf(0.00182f * dM, uM, (um1M - sM) * m) * rcpa(um1M + sM);

    float dN = Vn - 25.f;
    float uN = ex2a(dN * L9);
    float um1N = uN - 1.f;
    float sN = 0.005f * dN * fmaf(0.02f, uN, 0.002f);
    float nN = fmaf(0.0002f * dN, uN, (um1N - sN) * n) * rcpa(um1N + sN);

    float w  = ex2a((Vn + 90.f) * L12);
    float sH = fmaf(0.005f * BH_C, w * w, 0.00125f);
    float hN = fmaf(w - sH, h, 0.0025f) * rcpa(w + sH);

    if (Vn == 25.f)  nN = fmaf(0.99901f, n, 0.0018f) * (1.f / 1.00099f);
    if (Vn == -35.f) mN = fmaf(0.98623f, m, 0.01638f) * (1.f / 1.01377f);

    m = mN; n = nN; h = hN;
    V = Vn;
}

__device__ __forceinline__ float sigmoid_T(float V) {
    return rcpa(1.f + ex2a((20.f - V) * L3));
}

// ---------------------------------------------------------------------------
// K2: FUSED HH. One block per batch. Warps 0-3: 100 layer-1 chains (T1 -> smem);
// warps 4-6: z2 matvec (one step behind); warp 7: 10 layer-2 chains (two behind).
// One __syncthreads per step; the three stages overlap, so total wall time ~=
// one chain's latency instead of two chains + matvec.
// ---------------------------------------------------------------------------
__global__ void __launch_bounds__(256, 1)
hh_fused_kernel(const float* __restrict__ W2, float* __restrict__ out) {
    __shared__ float T1buf[2][104];   // entries 100..103 stay 0
    __shared__ float z2buf[2][16];

    const int b   = blockIdx.x;
    const int tid = threadIdx.x;

    float V = -70.f, m = 0.f, n = 0.f, h = 1.f;

    // G1 prefetch queue (g_z1 padded: loads up to row b*2000+2002 are in-bounds)
    float p0 = 0.f, p1 = 0.f, p2 = 0.f, p3 = 0.f;
    const float* zp = g_z1 + (size_t)b * T_STEPS * N1 + tid;

    // G2 weights
    float w[13];
    int g = 0, l = 0;
    const int o = tid - 224;

    if (tid < 100) {
        T1buf[0][tid] = S0V;
        p0 = zp[0];
        p1 = zp[100];
        p2 = zp[200];
        p3 = zp[300];
    }
    if (tid < 8) {
        T1buf[tid >> 2][100 + (tid & 3)] = 0.f;
    }
    if (tid >= 128 && tid < 224) {
        int u = tid - 128;
        g = u >> 3;
        l = u & 7;
#pragma unroll
        for (int i = 0; i < 13; i++) {
            int j = l + 8 * i;
            w[i] = (g < N2 && j < N1) ? W2[g * N1 + j] : 0.f;
        }
    }
    if (o >= 0 && o < N2) {
        out[(size_t)b * T_STEPS * N2 + o] = S0V;
    }
    __syncthreads();

    for (int t = 1; t < T_STEPS; ++t) {
        if (tid < 128) {
            // ---- G1: layer-1 neurons (compute V1[t], T1[t]) ----
            if (tid < 100) {
                float zc = p0;
                p0 = p1; p1 = p2; p2 = p3;
                p3 = zp[(size_t)(t + 3) * N1];   // unconditional (padded)
                hh_step(zc, V, m, n, h);
                T1buf[t & 1][tid] = sigmoid_T(V);
            }
        } else if (tid < 224) {
            // ---- G2: z2[t-1] = W2 @ T1[t-1] ----
            const float* tb = T1buf[(t - 1) & 1];
            float acc = 0.f;
#pragma unroll
            for (int i = 0; i < 13; i++)
                acc = fmaf(w[i], tb[l + 8 * i], acc);
            acc += __shfl_down_sync(0xffffffffu, acc, 4, 8);
            acc += __shfl_down_sync(0xffffffffu, acc, 2, 8);
            acc += __shfl_down_sync(0xffffffffu, acc, 1, 8);
            if (l == 0) z2buf[t & 1][g] = acc;
        } else {
            // ---- G3: layer-2 neurons, two steps behind (computes V2[t-1]) ----
            if (o < N2 && t >= 2) {
                float zk = z2buf[(t - 1) & 1][o];   // = z2[t-2]
                hh_step(zk, V, m, n, h);
                out[(size_t)b * T_STEPS * N2 + (size_t)(t - 1) * N2 + o] = sigmoid_T(V);
            }
        }
        __syncthreads();
    }

    // Epilogue: V2[T-1] uses z2[T-2]
    if (o >= 0 && o < N2) {
        float zk = z2buf[(T_STEPS - 1) & 1][o];
        hh_step(zk, V, m, n, h);
        out[(size_t)b * T_STEPS * N2 + (size_t)(T_STEPS - 1) * N2 + o] = sigmoid_T(V);
    }
}

// ---------------------------------------------------------------------------
extern "C" void kernel_launch(void* const* d_in, const int* in_sizes, int n_in,
                              void* d_out, int out_size) {
    const float* batch = (const float*)d_in[0];   // (100, 2000, 784)
    const float* W1    = (const float*)d_in[1];   // (100, 784)
    const float* W2    = (const float*)d_in[2];   // (10, 100)
    float* out = (float*)d_out;                   // (100, 2000, 10)

    w1_convert_kernel<<<(112 * K_DIM + 255) / 256, 256>>>(W1);
    gemm_z1_tc<<<(M_ROWS + 127) / 128, 256>>>(batch);
    hh_fused_kernel<<<BATCH, 256>>>(W2, out);
}